// round 1
// baseline (speedup 1.0000x reference)
#include <cuda_runtime.h>

// Problem constants
constexpr int Bn   = 8;
constexpr int Cn   = 128;
constexpr int Tn   = 32768;
constexpr int Ln   = 256;
constexpr int HOP  = 128;      // T / L
constexpr float SLOPE = 0.2f;

// Scratch (device globals: allocation-free rule)
__device__ float g_wt[(size_t)Bn * Ln * Cn * 3 * Cn];   // [b][l][ci][k][co]  402.7 MB
__device__ float g_h [(size_t)Bn * Cn * Tn];            // LVC output (post-leaky) 128 MB
__device__ float g_wn[Cn * 3 * Cn];                     // normalized conv weight [ci][k][co]

// ---------------- packed f32x2 helpers ----------------
static __device__ __forceinline__ unsigned long long pk2(float lo, float hi) {
    unsigned long long r;
    asm("mov.b64 %0, {%1, %2};" : "=l"(r) : "f"(lo), "f"(hi));
    return r;
}
static __device__ __forceinline__ void upk2(unsigned long long v, float &lo, float &hi) {
    asm("mov.b64 {%0, %1}, %2;" : "=f"(lo), "=f"(hi) : "l"(v));
}
static __device__ __forceinline__ void fma2(unsigned long long &d,
                                            unsigned long long a,
                                            unsigned long long b) {
    asm("fma.rn.f32x2 %0, %1, %2, %0;" : "+l"(d) : "l"(a), "l"(b));
}
static __device__ __forceinline__ float lrelu(float v) {
    return v > 0.f ? v : SLOPE * v;
}

// ---------------- weight-norm prep for the dilated conv ----------------
// g_wn[(ci*3 + k)*128 + co] = conv_g[co] * conv_v[co][ci][k] / ||conv_v[co]||
__global__ void wn_prep_kernel(const float* __restrict__ conv_v,
                               const float* __restrict__ conv_g) {
    __shared__ float sc[Cn];
    int co = threadIdx.x;
    float s = 0.f;
    #pragma unroll 4
    for (int i = 0; i < Cn * 3; ++i) {
        float t = conv_v[co * (Cn * 3) + i];
        s += t * t;
    }
    sc[co] = conv_g[co] / sqrtf(s);
    __syncthreads();
    for (int i = threadIdx.x; i < Cn * 3 * Cn; i += Cn) {
        int c2   = i & (Cn - 1);
        int rest = i >> 7;          // ci*3 + k
        int k    = rest % 3;
        int ci   = rest / 3;
        g_wn[i] = conv_v[(c2 * Cn + ci) * 3 + k] * sc[c2];
    }
}

// ---------------- LVC weight transpose ----------------
// W[b][ci][co][k][l]  ->  g_wt[b][l][ci][k][co]   (both coalesced via 32x32 tile)
__global__ void transpose_w_kernel(const float* __restrict__ W) {
    __shared__ float tile[32][33];
    int z  = blockIdx.z;          // b*128*3 + ci*3 + k  (3072 total)
    int k  = z % 3;
    int ci = (z / 3) & (Cn - 1);
    int b  = z / (3 * Cn);
    int co0 = blockIdx.y * 32;
    int l0  = blockIdx.x * 32;

    #pragma unroll
    for (int j = 0; j < 4; ++j) {
        int co = co0 + threadIdx.y + j * 8;
        tile[threadIdx.y + j * 8][threadIdx.x] =
            W[((((size_t)b * Cn + ci) * Cn + co) * 3 + k) * Ln + l0 + threadIdx.x];
    }
    __syncthreads();
    #pragma unroll
    for (int j = 0; j < 4; ++j) {
        int l = l0 + threadIdx.y + j * 8;
        g_wt[((((size_t)b * Ln + l) * Cn + ci) * 3 + k) * Cn + co0 + threadIdx.x] =
            tile[threadIdx.x][threadIdx.y + j * 8];
    }
}

// ---------------- Kernel A: location-variable conv + bias + leaky ----------------
// One CTA per (b, l). 256 threads: tx (16) -> 8 s each, ty (16) -> 8 co each.
constexpr int XS_PAD_A = 132;                       // 130 cols, padded (16B-mult stride)
constexpr int SMEM_A = (Cn * XS_PAD_A + 16 * 3 * Cn) * 4;

__global__ __launch_bounds__(256)
void lvc_kernel(const float* __restrict__ x, const float* __restrict__ bias) {
    const int b = blockIdx.x >> 8;
    const int l = blockIdx.x & 255;
    const int tid = threadIdx.x;
    const int tx = tid & 15, ty = tid >> 4;
    const int s0 = tx * 8, co0 = ty * 8;

    extern __shared__ float sm[];
    float* xs = sm;                   // [128][132], cols 0..129 valid
    float* ws = sm + Cn * XS_PAD_A;   // [16][3][128]

    // load x window: t = l*128 - 1 + c, c in [0,130)
    const int tbase = l * HOP - 1;
    for (int i = tid; i < Cn * 130; i += 256) {
        int ci = i / 130, c = i - ci * 130;
        int t = tbase + c;
        float v = (t >= 0 && t < Tn) ? x[(b * Cn + ci) * Tn + t] : 0.f;
        xs[ci * XS_PAD_A + c] = v;
    }

    // accumulators: co pairs x 8 s, init with bias
    unsigned long long acc[4][8];
    #pragma unroll
    for (int cp = 0; cp < 4; ++cp) {
        int co = co0 + 2 * cp;
        unsigned long long bb = pk2(bias[(b * Cn + co) * Ln + l],
                                    bias[(b * Cn + co + 1) * Ln + l]);
        #pragma unroll
        for (int s = 0; s < 8; ++s) acc[cp][s] = bb;
    }

    const float* wt_blk = g_wt + (size_t)(b * Ln + l) * (Cn * 3 * Cn);

    #pragma unroll 1
    for (int ci0 = 0; ci0 < Cn; ci0 += 16) {
        __syncthreads();
        const float4* src = (const float4*)(wt_blk + (size_t)ci0 * 384);
        float4* dst = (float4*)ws;
        #pragma unroll
        for (int i = tid; i < 1536; i += 256) dst[i] = src[i];
        __syncthreads();

        #pragma unroll 1
        for (int cc = 0; cc < 16; ++cc) {
            const float* xr = xs + (ci0 + cc) * XS_PAD_A + s0;
            float4 a  = *(const float4*)(xr);
            float4 bq = *(const float4*)(xr + 4);
            float2 cq = *(const float2*)(xr + 8);
            float xv[10] = {a.x, a.y, a.z, a.w, bq.x, bq.y, bq.z, bq.w, cq.x, cq.y};
            unsigned long long xb[10];
            #pragma unroll
            for (int j = 0; j < 10; ++j) xb[j] = pk2(xv[j], xv[j]);

            #pragma unroll
            for (int k = 0; k < 3; ++k) {
                #pragma unroll
                for (int cp = 0; cp < 4; ++cp) {
                    unsigned long long w2 =
                        *(const unsigned long long*)(ws + cc * 384 + k * Cn + co0 + 2 * cp);
                    #pragma unroll
                    for (int s = 0; s < 8; ++s) fma2(acc[cp][s], xb[s + k], w2);
                }
            }
        }
    }

    // store with leaky relu (vectorized)
    #pragma unroll
    for (int cp = 0; cp < 4; ++cp) {
        int co = co0 + 2 * cp;
        float r0[8], r1[8];
        #pragma unroll
        for (int s = 0; s < 8; ++s) {
            float v0, v1;
            upk2(acc[cp][s], v0, v1);
            r0[s] = lrelu(v0); r1[s] = lrelu(v1);
        }
        float* o0 = g_h + (size_t)(b * Cn + co) * Tn + l * HOP + s0;
        float* o1 = o0 + Tn;
        *(float4*)(o0)     = make_float4(r0[0], r0[1], r0[2], r0[3]);
        *(float4*)(o0 + 4) = make_float4(r0[4], r0[5], r0[6], r0[7]);
        *(float4*)(o1)     = make_float4(r1[0], r1[1], r1[2], r1[3]);
        *(float4*)(o1 + 4) = make_float4(r1[4], r1[5], r1[6], r1[7]);
    }
}

// ---------------- Kernel B: dilated conv (dil=3) + bias + leaky ----------------
// One CTA per (b, 128-wide t tile). Needs h cols [t0-3, t0+130] -> 134 cols.
constexpr int XS_PAD_B = 136;
constexpr int SMEM_B = (Cn * XS_PAD_B + 16 * 3 * Cn) * 4;

__global__ __launch_bounds__(256)
void dconv_kernel(const float* __restrict__ conv_b, float* __restrict__ out) {
    const int b  = blockIdx.x >> 8;
    const int tt = blockIdx.x & 255;
    const int t0 = tt * HOP;
    const int tid = threadIdx.x;
    const int tx = tid & 15, ty = tid >> 4;
    const int s0 = tx * 8, co0 = ty * 8;

    extern __shared__ float sm[];
    float* hs = sm;                   // [128][136], cols 0..133 valid
    float* ws = sm + Cn * XS_PAD_B;   // [16][3][128]

    const int tbase = t0 - 3;
    for (int i = tid; i < Cn * 134; i += 256) {
        int ci = i / 134, c = i - ci * 134;
        int t = tbase + c;
        float v = (t >= 0 && t < Tn) ? g_h[(size_t)(b * Cn + ci) * Tn + t] : 0.f;
        hs[ci * XS_PAD_B + c] = v;
    }

    unsigned long long acc[4][8];
    #pragma unroll
    for (int cp = 0; cp < 4; ++cp) {
        int co = co0 + 2 * cp;
        unsigned long long bb = pk2(conv_b[co], conv_b[co + 1]);
        #pragma unroll
        for (int s = 0; s < 8; ++s) acc[cp][s] = bb;
    }

    #pragma unroll 1
    for (int ci0 = 0; ci0 < Cn; ci0 += 16) {
        __syncthreads();
        const float4* src = (const float4*)(g_wn + (size_t)ci0 * 384);
        float4* dst = (float4*)ws;
        #pragma unroll
        for (int i = tid; i < 1536; i += 256) dst[i] = src[i];
        __syncthreads();

        #pragma unroll 1
        for (int cc = 0; cc < 16; ++cc) {
            const float* xr = hs + (ci0 + cc) * XS_PAD_B + s0;
            float4 a  = *(const float4*)(xr);
            float4 bq = *(const float4*)(xr + 4);
            float4 cq = *(const float4*)(xr + 8);
            float2 dq = *(const float2*)(xr + 12);
            float xv[14] = {a.x, a.y, a.z, a.w, bq.x, bq.y, bq.z, bq.w,
                            cq.x, cq.y, cq.z, cq.w, dq.x, dq.y};
            unsigned long long xb[14];
            #pragma unroll
            for (int j = 0; j < 14; ++j) xb[j] = pk2(xv[j], xv[j]);

            #pragma unroll
            for (int k = 0; k < 3; ++k) {
                #pragma unroll
                for (int cp = 0; cp < 4; ++cp) {
                    unsigned long long w2 =
                        *(const unsigned long long*)(ws + cc * 384 + k * Cn + co0 + 2 * cp);
                    #pragma unroll
                    for (int s = 0; s < 8; ++s) fma2(acc[cp][s], xb[s + 3 * k], w2);
                }
            }
        }
    }

    #pragma unroll
    for (int cp = 0; cp < 4; ++cp) {
        int co = co0 + 2 * cp;
        float r0[8], r1[8];
        #pragma unroll
        for (int s = 0; s < 8; ++s) {
            float v0, v1;
            upk2(acc[cp][s], v0, v1);
            r0[s] = lrelu(v0); r1[s] = lrelu(v1);
        }
        float* o0 = out + (size_t)(b * Cn + co) * Tn + t0 + s0;
        float* o1 = o0 + Tn;
        *(float4*)(o0)     = make_float4(r0[0], r0[1], r0[2], r0[3]);
        *(float4*)(o0 + 4) = make_float4(r0[4], r0[5], r0[6], r0[7]);
        *(float4*)(o1)     = make_float4(r1[0], r1[1], r1[2], r1[3]);
        *(float4*)(o1 + 4) = make_float4(r1[4], r1[5], r1[6], r1[7]);
    }
}

// ---------------- launch ----------------
extern "C" void kernel_launch(void* const* d_in, const int* in_sizes, int n_in,
                              void* d_out, int out_size) {
    const float* x      = (const float*)d_in[0];
    const float* weight = (const float*)d_in[1];
    const float* bias   = (const float*)d_in[2];
    const float* conv_v = (const float*)d_in[3];
    const float* conv_g = (const float*)d_in[4];
    const float* conv_b = (const float*)d_in[5];
    float* out = (float*)d_out;

    cudaFuncSetAttribute(lvc_kernel,  cudaFuncAttributeMaxDynamicSharedMemorySize, SMEM_A);
    cudaFuncSetAttribute(dconv_kernel, cudaFuncAttributeMaxDynamicSharedMemorySize, SMEM_B);

    wn_prep_kernel<<<1, Cn>>>(conv_v, conv_g);
    transpose_w_kernel<<<dim3(Ln / 32, Cn / 32, Bn * Cn * 3), dim3(32, 8)>>>(weight);
    lvc_kernel<<<Bn * Ln, 256, SMEM_A>>>(x, bias);
    dconv_kernel<<<Bn * Ln, 256, SMEM_B>>>(conv_b, out);
}